// round 6
// baseline (speedup 1.0000x reference)
#include <cuda_runtime.h>

// x: (B=16, C=256, L=16384) fp32, kernel=4, stride=4 -> out (B, 256, 4096) fp32
#define C_CH    256
#define L_IN    16384
#define OUT_LEN 4096
#define EPS_F   1e-7f
#define STAGE_STRIDE 40   // floats per staged channel row (32 used + 8 pad)

// Block: 256 threads = 8 warps, owns 32 consecutive output columns x 256 ch.
// 4 tiles of 8 columns; per tile the layout is exactly R2's:
//   thread t: column j = t&7, channel group cg = t>>3, channels cg+32i (i<8)
//   -> per-warp 128B contiguous read runs per channel row.
// Results are staged in smem; one cooperative writeback at the end emits
// full 128B lines (STG.128 x 8 lanes per row), one owner per output line.
__global__ __launch_bounds__(256) void hpool_kernel(
    const float* __restrict__ x, float* __restrict__ out)
{
    __shared__ float stage[C_CH * STAGE_STRIDE];   // 40 KB
    __shared__ float red[8][8][10];
    __shared__ float gsum[8][10];
    __shared__ float cf[8][4];

    const int t    = threadIdx.x;
    const int j    = t & 7;
    const int cg   = t >> 3;       // 0..31
    const int lane = t & 31;
    const int warp = t >> 5;
    const int b    = blockIdx.y;
    const int col_base = blockIdx.x * 32;

    const size_t xbase = (size_t)b * (C_CH * L_IN) + (size_t)(col_base + j) * 4;

#pragma unroll
    for (int k = 0; k < 4; k++) {
        // ---- load tile k window: 8 channels x 4 positions ----
        float4 w[8];
#pragma unroll
        for (int i = 0; i < 8; i++) {
            w[i] = *reinterpret_cast<const float4*>(
                x + xbase + (size_t)k * 32 + (size_t)(cg + 32 * i) * L_IN);
        }

        // ---- Gram partials: diag(0..3), off (0,1)(0,2)(0,3)(1,2)(1,3)(2,3) ----
        float s[10];
#pragma unroll
        for (int q = 0; q < 10; q++) s[q] = 0.f;
#pragma unroll
        for (int i = 0; i < 8; i++) {
            const float a0 = w[i].x, a1 = w[i].y, a2 = w[i].z, a3 = w[i].w;
            s[0] += a0 * a0; s[1] += a1 * a1; s[2] += a2 * a2; s[3] += a3 * a3;
            s[4] += a0 * a1; s[5] += a0 * a2; s[6] += a0 * a3;
            s[7] += a1 * a2; s[8] += a1 * a3; s[9] += a2 * a3;
        }
#pragma unroll
        for (int q = 0; q < 10; q++) {
            s[q] += __shfl_xor_sync(0xffffffffu, s[q], 8);
            s[q] += __shfl_xor_sync(0xffffffffu, s[q], 16);
        }

        if (lane < 8) {
#pragma unroll
            for (int q = 0; q < 10; q++) red[warp][lane][q] = s[q];
        }
        __syncthreads();

        if (t < 80) {
            const int col = t / 10, q = t % 10;
            float v = 0.f;
#pragma unroll
            for (int wq = 0; wq < 8; wq++) v += red[wq][col][q];
            gsum[col][q] = v;
        }
        __syncthreads();

        if (t < 8) {
            float G[10];
#pragma unroll
            for (int q = 0; q < 10; q++) G[q] = gsum[t][q];

            float f[4], gam[4], denom = 0.f;
#pragma unroll
            for (int p = 0; p < 4; p++) {
                f[p] = 2.0f / (1.0f + G[p]);
                gam[p] = rsqrtf(fmaxf(1.0f - f[p] * f[p] * G[p], EPS_F));
                denom += gam[p];
            }
            const float inv_d = 1.0f / denom;
            const float c0 = gam[0] * f[0] * inv_d;
            const float c1 = gam[1] * f[1] * inv_d;
            const float c2 = gam[2] * f[2] * inv_d;
            const float c3 = gam[3] * f[3] * inv_d;

            const float mk2 =
                c0 * c0 * G[0] + c1 * c1 * G[1] + c2 * c2 * G[2] + c3 * c3 * G[3] +
                2.0f * (c0 * c1 * G[4] + c0 * c2 * G[5] + c0 * c3 * G[6] +
                        c1 * c2 * G[7] + c1 * c3 * G[8] + c2 * c3 * G[9]);

            const float sc = 1.0f / (1.0f + sqrtf(fmaxf(1.0f - mk2, EPS_F)));
            cf[t][0] = c0 * sc;
            cf[t][1] = c1 * sc;
            cf[t][2] = c2 * sc;
            cf[t][3] = c3 * sc;
        }
        __syncthreads();

        // ---- stage m into smem (conflict-free: (40*ch + j) mod 32 distinct) ----
        const float c0 = cf[j][0], c1 = cf[j][1], c2 = cf[j][2], c3 = cf[j][3];
#pragma unroll
        for (int i = 0; i < 8; i++) {
            stage[(cg + 32 * i) * STAGE_STRIDE + k * 8 + j] =
                c0 * w[i].x + c1 * w[i].y + c2 * w[i].z + c3 * w[i].w;
        }
        __syncthreads();
    }

    // ---- cooperative writeback: full 128B lines, one owner per line ----
    // pass g: warp covers 4 channel rows; lanes 0-7 -> one row's 32 cols
    // as 8 x STG.128 = one full 128B line per row per instruction.
    const size_t obase = (size_t)b * (C_CH * OUT_LEN) + col_base;
    const int row0  = t >> 3;     // 0..31
    const int chunk = t & 7;      // 0..7 (float4 index within the row)
#pragma unroll
    for (int g = 0; g < 8; g++) {
        const int row = row0 + 32 * g;
        const float4 v = *reinterpret_cast<const float4*>(
            &stage[row * STAGE_STRIDE + chunk * 4]);
        float4* dst = reinterpret_cast<float4*>(
            out + obase + (size_t)row * OUT_LEN + chunk * 4);
        __stcs(dst, v);
    }
}

extern "C" void kernel_launch(void* const* d_in, const int* in_sizes, int n_in,
                              void* d_out, int out_size)
{
    const float* x = (const float*)d_in[0];
    float* out = (float*)d_out;

    const int B = in_sizes[0] / (C_CH * L_IN);   // 16
    dim3 grid(OUT_LEN / 32, B);                  // (128, 16)
    hpool_kernel<<<grid, 256>>>(x, out);
}

// round 7
// speedup vs baseline: 1.2903x; 1.2903x over previous
#include <cuda_runtime.h>

// x: (B=16, C=256, L=16384) fp32, kernel=4, stride=4 -> out (B, 256, 4096) fp32
// c_curv = 1.0, eps = 1e-7
#define C_CH    256
#define L_IN    16384
#define OUT_LEN 4096
#define EPS_F   1e-7f

// Block: 256 threads = 8 warps, covering 8 output columns x all 256 channels.
// Thread t: column j = t&7, channel group cg = t>>3 (0..31), channels cg+32i.
// Reads: per-warp 128B contiguous runs (8 cols x 4 floats) per channel row.
// Writes: 8 consecutive floats per channel row = exactly one full 32B sector;
//         the 4 sibling blocks' sectors merge into full 128B lines in L2.
// Reduction: 4x4 window Gram matrix (10 sums) -> x2_p = G_pp, mK2 = c^T G c.
__global__ __launch_bounds__(256) void hpool_kernel(
    const float* __restrict__ x, float* __restrict__ out)
{
    const int t    = threadIdx.x;
    const int j    = t & 7;
    const int cg   = t >> 3;       // 0..31
    const int lane = t & 31;
    const int warp = t >> 5;
    const int l0   = blockIdx.x * 8;
    const int b    = blockIdx.y;

    // ---- load window: 8 channels x 4 positions, one float4 each ----
    // All offsets fit in 32 bits (max 268M bytes / 67M elements).
    const unsigned base_in = (unsigned)b * (C_CH * L_IN) + (unsigned)(l0 + j) * 4;
    float4 w[8];
#pragma unroll
    for (int i = 0; i < 8; i++) {
        const float4* p = reinterpret_cast<const float4*>(
            x + base_in + (unsigned)(cg + 32 * i) * L_IN);
        w[i] = __ldcs(p);   // read-once stream: evict-first, keep L2 for writes
    }

    // ---- Gram partials: q0..3 = diag; q4..9 = (0,1)(0,2)(0,3)(1,2)(1,3)(2,3) ----
    float s[10];
#pragma unroll
    for (int q = 0; q < 10; q++) s[q] = 0.f;
#pragma unroll
    for (int i = 0; i < 8; i++) {
        const float a0 = w[i].x, a1 = w[i].y, a2 = w[i].z, a3 = w[i].w;
        s[0] += a0 * a0; s[1] += a1 * a1; s[2] += a2 * a2; s[3] += a3 * a3;
        s[4] += a0 * a1; s[5] += a0 * a2; s[6] += a0 * a3;
        s[7] += a1 * a2; s[8] += a1 * a3; s[9] += a2 * a3;
    }
    // reduce across the 4 channel-group lanes sharing column j
#pragma unroll
    for (int q = 0; q < 10; q++) {
        s[q] += __shfl_xor_sync(0xffffffffu, s[q], 8);
        s[q] += __shfl_xor_sync(0xffffffffu, s[q], 16);
    }

    __shared__ float red[8][8][10];   // [warp][col][q]
    __shared__ float gsum[8][10];     // [col][q]
    __shared__ float cf[8][4];        // [col][p] fused coefficients
    if (lane < 8) {
#pragma unroll
        for (int q = 0; q < 10; q++) red[warp][lane][q] = s[q];
    }
    __syncthreads();

    // cross-warp sum: 80 (col,q) cells, one thread each
    if (t < 80) {
        const int col = t / 10, q = t % 10;
        float v = 0.f;
#pragma unroll
        for (int wq = 0; wq < 8; wq++) v += red[wq][col][q];
        gsum[col][q] = v;
    }
    __syncthreads();

    // per-column scalar math (one thread per column)
    if (t < 8) {
        float G[10];
#pragma unroll
        for (int q = 0; q < 10; q++) G[q] = gsum[t][q];

        float f[4], gam[4], denom = 0.f;
#pragma unroll
        for (int p = 0; p < 4; p++) {
            f[p] = 2.0f / (1.0f + G[p]);
            gam[p] = rsqrtf(fmaxf(1.0f - f[p] * f[p] * G[p], EPS_F));
            denom += gam[p];
        }
        const float inv_d = 1.0f / denom;
        const float c0 = gam[0] * f[0] * inv_d;
        const float c1 = gam[1] * f[1] * inv_d;
        const float c2 = gam[2] * f[2] * inv_d;
        const float c3 = gam[3] * f[3] * inv_d;

        const float mk2 =
            c0 * c0 * G[0] + c1 * c1 * G[1] + c2 * c2 * G[2] + c3 * c3 * G[3] +
            2.0f * (c0 * c1 * G[4] + c0 * c2 * G[5] + c0 * c3 * G[6] +
                    c1 * c2 * G[7] + c1 * c3 * G[8] + c2 * c3 * G[9]);

        const float sc = 1.0f / (1.0f + sqrtf(fmaxf(1.0f - mk2, EPS_F)));
        cf[t][0] = c0 * sc;
        cf[t][1] = c1 * sc;
        cf[t][2] = c2 * sc;
        cf[t][3] = c3 * sc;
    }
    __syncthreads();

    // ---- fused epilogue: out = sum_p cf[j][p] * w[:,p] ----
    const float c0 = cf[j][0], c1 = cf[j][1], c2 = cf[j][2], c3 = cf[j][3];
    const unsigned base_out = (unsigned)b * (C_CH * OUT_LEN) + (unsigned)(l0 + j);
#pragma unroll
    for (int i = 0; i < 8; i++) {
        out[base_out + (unsigned)(cg + 32 * i) * OUT_LEN] =
            c0 * w[i].x + c1 * w[i].y + c2 * w[i].z + c3 * w[i].w;
    }
}

extern "C" void kernel_launch(void* const* d_in, const int* in_sizes, int n_in,
                              void* d_out, int out_size)
{
    const float* x = (const float*)d_in[0];
    float* out = (float*)d_out;

    const int B = in_sizes[0] / (C_CH * L_IN);   // 16
    dim3 grid(OUT_LEN / 8, B);                   // (512, 16)
    hpool_kernel<<<grid, 256>>>(x, out);
}